// round 16
// baseline (speedup 1.0000x reference)
#include <cuda_runtime.h>
#include <cuda_bf16.h>
#include <math_constants.h>
#include <cstdint>

#define NROWS 32768
#define NCODES 8192
#define DIM 512
#define NELEM (NROWS * DIM)          // 16777216
#define LOSS_PARTIALS 2048
#define MAXC 64
#define MARGIN 4e-4f

#define NT_TILES 44                  // tensor-class n-tiles (codes 0..5631)
#define NT_CODES (NT_TILES * 128)
#define NS_TILES 20                  // SIMT-class n-tiles (codes 5632..8191)

// ---------------------------------------------------------------------------
// Device globals (scratch; no runtime allocation allowed)
// ---------------------------------------------------------------------------
__device__ __nv_bfloat16 g_Xb[(size_t)NROWS * DIM];   // ~33.5 MB
__device__ __nv_bfloat16 g_Eb[(size_t)NCODES * DIM];  // ~8.4 MB
__device__ float  g_rownorm[NROWS];
__device__ float  g_codenorm[NCODES];
__device__ int    g_argmin[NROWS];
__device__ int    g_candCount[NROWS];
__device__ int    g_candIdx[(size_t)NROWS * MAXC];    // 8 MB
__device__ unsigned long long g_best[NROWS];          // packed (dist_bits, idx)
__device__ double g_partial[LOSS_PARTIALS];

// ---------------------------------------------------------------------------
// Arch-neutral PTX helpers
// ---------------------------------------------------------------------------
__device__ __forceinline__ uint32_t smem_to_u32(const void* p) {
    uint32_t a;
    asm("{ .reg .u64 t; cvta.to.shared.u64 t, %1; cvt.u32.u64 %0, t; }"
        : "=r"(a) : "l"(p));
    return a;
}
#define CP_ASYNC16(dst, src) \
    asm volatile("cp.async.cg.shared.global [%0], [%1], 16;" :: "r"(dst), "l"(src) : "memory")
#define CP_COMMIT() asm volatile("cp.async.commit_group;" ::: "memory")
#define CP_WAIT1()  asm volatile("cp.async.wait_group 1;" ::: "memory")
#define BAR_T() asm volatile("bar.sync 1, 128;" ::: "memory")   // tensor warps 0-3
#define BAR_S() asm volatile("bar.sync 2, 128;" ::: "memory")   // simt warps 4-7

__device__ __forceinline__ void ldsm_x4(uint32_t* r, uint32_t addr) {
    asm volatile("ldmatrix.sync.aligned.m8n8.x4.shared.b16 {%0,%1,%2,%3}, [%4];"
        : "=r"(r[0]), "=r"(r[1]), "=r"(r[2]), "=r"(r[3]) : "r"(addr));
}
__device__ __forceinline__ void mma16816(float* c, const uint32_t* a, const uint32_t* b) {
    asm volatile(
        "mma.sync.aligned.m16n8k16.row.col.f32.bf16.bf16.f32 "
        "{%0,%1,%2,%3}, {%4,%5,%6,%7}, {%8,%9}, {%0,%1,%2,%3};"
        : "+f"(c[0]), "+f"(c[1]), "+f"(c[2]), "+f"(c[3])
        : "r"(a[0]), "r"(a[1]), "r"(a[2]), "r"(a[3]), "r"(b[0]), "r"(b[1]));
}

// smem layout (dynamic). 111,872 B -> 2 CTAs/SM.
#define OFF_A     0         // tensor A: 64 x 512 bf16, XOR-swizzled = 65536 B
#define OFF_B     65536     // tensor B: 2 x (128 x 64 bf16)         = 32768 B
#define OFF_CN    98304     // 2 x 128 floats codenorm               =  1024 B
#define OFF_RMIN  99328     // 64 floats running row-min (shared)    =   256 B
#define OFF_SAS   99584     // simt As: 16 x 64 fp32                 =  4096 B
#define OFF_SBS   103680    // simt Bs: 16 x 128 fp32                =  8192 B
#define FUSED_SMEM 111872

// ---------------------------------------------------------------------------
// Kernel 0: fp32 -> bf16 conversion (+ init candidate counters / g_best)
// ---------------------------------------------------------------------------
__global__ void convert_kernel(const float* __restrict__ X, const float* __restrict__ E) {
    const int t  = blockIdx.x * blockDim.x + threadIdx.x;
    const int nX = NELEM / 4;
    const int nE = NCODES * DIM / 4;
    if (t < nX) {
        float4 v = reinterpret_cast<const float4*>(X)[t];
        __nv_bfloat162 p0, p1;
        p0.x = __float2bfloat16_rn(v.x); p0.y = __float2bfloat16_rn(v.y);
        p1.x = __float2bfloat16_rn(v.z); p1.y = __float2bfloat16_rn(v.w);
        reinterpret_cast<__nv_bfloat162*>(g_Xb)[t * 2]     = p0;
        reinterpret_cast<__nv_bfloat162*>(g_Xb)[t * 2 + 1] = p1;
    } else if (t < nX + nE) {
        int u = t - nX;
        float4 v = reinterpret_cast<const float4*>(E)[u];
        __nv_bfloat162 p0, p1;
        p0.x = __float2bfloat16_rn(v.x); p0.y = __float2bfloat16_rn(v.y);
        p1.x = __float2bfloat16_rn(v.z); p1.y = __float2bfloat16_rn(v.w);
        reinterpret_cast<__nv_bfloat162*>(g_Eb)[u * 2]     = p0;
        reinterpret_cast<__nv_bfloat162*>(g_Eb)[u * 2 + 1] = p1;
    }
    if (t < NROWS) {
        g_candCount[t] = 0;
        g_best[t] = 0xFFFFFFFFFFFFFFFFull;
    }
}

// ---------------------------------------------------------------------------
// Kernel A: row norms of X and code norms of E (one warp per vector)
// ---------------------------------------------------------------------------
__global__ void norms_kernel(const float* __restrict__ X, const float* __restrict__ E) {
    int gwarp = (blockIdx.x * blockDim.x + threadIdx.x) >> 5;
    int lane  = threadIdx.x & 31;
    const float* p;
    if (gwarp < NROWS)                p = X + (size_t)gwarp * DIM;
    else if (gwarp < NROWS + NCODES)  p = E + (size_t)(gwarp - NROWS) * DIM;
    else return;
    float s = 0.f;
    #pragma unroll
    for (int t = 0; t < DIM / 32; t++) { float v = p[lane + t * 32]; s = __fmaf_rn(v, v, s); }
    #pragma unroll
    for (int o = 16; o > 0; o >>= 1) s += __shfl_xor_sync(0xffffffffu, s, o);
    if (lane == 0) {
        if (gwarp < NROWS) g_rownorm[gwarp] = s;
        else               g_codenorm[gwarp - NROWS] = s;
    }
}

// ---------------------------------------------------------------------------
// Tensor-class body (warps 0-3): 4-warp machinery (warp tile 32x64),
//   codes [0, NT_CODES), margin-candidate output.
// ---------------------------------------------------------------------------
__device__ void tensor_body(char* smem, int ctid, int mBase) {
    const int wid  = ctid >> 5;           // 0..3
    const int lane = ctid & 31;
    const int wm   = wid & 1;             // warp row block (32 rows)
    const int wn   = wid >> 1;            // warp col block (64 cols), 0..1
    const uint32_t sbase = smem_to_u32(smem);
    float* rmin = reinterpret_cast<float*>(smem + OFF_RMIN);
    const uint4* Eb4 = reinterpret_cast<const uint4*>(g_Eb);

    float cr[4];
    #pragma unroll
    for (int mi = 0; mi < 2; mi++)
        #pragma unroll
        for (int h = 0; h < 2; h++)
            cr[mi * 2 + h] = g_rownorm[mBase + wm * 32 + mi * 16 + (lane >> 2) + h * 8];

    uint32_t aBase[2]; int aS[2];
    #pragma unroll
    for (int mi = 0; mi < 2; mi++) {
        int row = wm * 32 + mi * 16 + (lane & 7) + ((lane >> 3) & 1) * 8;
        aBase[mi] = sbase + OFF_A + row * 1024;
        aS[mi] = row & 7;
    }
    uint32_t bRow[4]; int bS[4];
    #pragma unroll
    for (int np = 0; np < 4; np++) {
        int n = wn * 64 + np * 16 + (lane & 7) + ((lane >> 4) & 1) * 8;
        bRow[np] = n * 128;
        bS[np] = n & 7;
    }
    const int aCb = (lane >> 4) & 1;
    const int bCb = (lane >> 3) & 1;

    float acc[2][8][4];
    const int NCHUNK = NT_TILES * 8;          // 352

    for (int t = 0; t < NCHUNK; t++) {
        CP_WAIT1();
        BAR_T();

        const int kc = t & 7;
        if (kc == 0) {
            #pragma unroll
            for (int mi = 0; mi < 2; mi++)
                #pragma unroll
                for (int j = 0; j < 8; j++)
                    #pragma unroll
                    for (int q = 0; q < 4; q++) acc[mi][j][q] = 0.f;
        }

        const uint32_t bBufBase = sbase + OFF_B + (t & 1) * 16384;
        #pragma unroll
        for (int ks = 0; ks < 4; ks++) {
            uint32_t a[2][4], b[4][4];
            const int aC = kc * 8 + ks * 2 + aCb;
            const int bC = ks * 2 + bCb;
            #pragma unroll
            for (int mi = 0; mi < 2; mi++)
                ldsm_x4(a[mi], aBase[mi] + ((aC ^ aS[mi]) << 4));
            #pragma unroll
            for (int np = 0; np < 4; np++)
                ldsm_x4(b[np], bBufBase + bRow[np] + ((bC ^ bS[np]) << 4));
            #pragma unroll
            for (int mi = 0; mi < 2; mi++)
                #pragma unroll
                for (int np = 0; np < 4; np++) {
                    mma16816(acc[mi][np * 2],     a[mi], &b[np][0]);
                    mma16816(acc[mi][np * 2 + 1], a[mi], &b[np][2]);
                }
        }

        if (kc == 7) {
            const int nt = t >> 3;
            const float* cn = reinterpret_cast<const float*>(smem + OFF_CN + (nt & 1) * 512);
            #pragma unroll
            for (int mi = 0; mi < 2; mi++) {
                #pragma unroll
                for (int h = 0; h < 2; h++) {
                    const int rloc = wm * 32 + mi * 16 + (lane >> 2) + h * 8;
                    const float crv = cr[mi * 2 + h];
                    const float rm  = rmin[rloc];
                    float d[16];
                    float lmin = CUDART_INF_F;
                    #pragma unroll
                    for (int j = 0; j < 8; j++) {
                        #pragma unroll
                        for (int cb = 0; cb < 2; cb++) {
                            float sc = cn[wn * 64 + j * 8 + (lane & 3) * 2 + cb];
                            float v = __fmaf_rn(-2.0f, acc[mi][j][h * 2 + cb], crv + sc);
                            d[j * 2 + cb] = v;
                            lmin = fminf(lmin, v);
                        }
                    }
                    const float thr = fminf(rm, lmin) + MARGIN;
                    bool has = false;
                    #pragma unroll
                    for (int j = 0; j < 16; j++) has |= (d[j] < thr);
                    if (__any_sync(0xffffffffu, has)) {
                        #pragma unroll
                        for (int j = 0; j < 16; j++) {
                            if (d[j] < thr) {
                                int idx  = nt * 128 + wn * 64 + (j >> 1) * 8 + (lane & 3) * 2 + (j & 1);
                                int grow = mBase + rloc;
                                int pos = atomicAdd(&g_candCount[grow], 1);
                                if (pos < MAXC) g_candIdx[(size_t)grow * MAXC + pos] = idx;
                            }
                        }
                    }
                    float m2 = fminf(lmin, __shfl_xor_sync(0xffffffffu, lmin, 1));
                    m2 = fminf(m2, __shfl_xor_sync(0xffffffffu, m2, 2));
                    if ((lane & 3) == 0)
                        atomicMin(reinterpret_cast<int*>(&rmin[rloc]), __float_as_int(m2));
                }
            }
        }

        BAR_T();                              // tensor warps done reading buffer t&1

        if (t + 2 < NCHUNK) {
            const int tn = t + 2, ntn = tn >> 3, kcn = tn & 7;
            #pragma unroll
            for (int n = 0; n < 8; n++) {
                int i = ctid + n * 128;
                int r = i >> 3, c = i & 7;
                uint32_t dst = sbase + OFF_B + (t & 1) * 16384 + r * 128 + ((c ^ (r & 7)) << 4);
                CP_ASYNC16(dst, Eb4 + (size_t)(ntn * 128 + r) * 64 + kcn * 8 + c);
            }
            if (kcn == 0 && ctid < 32) {
                uint32_t dst = sbase + OFF_CN + (ntn & 1) * 512 + ctid * 16;
                CP_ASYNC16(dst, reinterpret_cast<const uint4*>(g_codenorm + ntn * 128) + ctid);
            }
        }
        CP_COMMIT();
    }
}

// ---------------------------------------------------------------------------
// SIMT-class body (warps 4-7): exact fp32 FFMA, codes [NT_CODES, 8192).
//   Register-resident argmin (reference tie-break); ONE packed atomicMin per
//   (row, column-group) at the end.
// ---------------------------------------------------------------------------
__device__ void simt_body(char* smem, int ctid, int mBase,
                          const float* __restrict__ X, const float* __restrict__ E) {
    float* sAs = reinterpret_cast<float*>(smem + OFF_SAS);   // [16][64]
    float* sBs = reinterpret_cast<float*>(smem + OFF_SBS);   // [16][128]
    float* rmin = reinterpret_cast<float*>(smem + OFF_RMIN);

    const int tx = ctid & 15;          // 16 col groups (8 codes each)
    const int ty = ctid >> 4;          // 8 row groups (8 rows each)

    const int lrowA = ctid >> 1;       // 0..63
    const int lkpA  = (ctid & 1) * 2;  // 0 or 2

    const float4* __restrict__ Xv = reinterpret_cast<const float4*>(X);
    const float4* __restrict__ Ev = reinterpret_cast<const float4*>(E);

    float cr[8];
    float bestD[8];
    int   bestI[8];
    #pragma unroll
    for (int i = 0; i < 8; i++) {
        cr[i]    = g_rownorm[mBase + ty * 8 + i];
        bestD[i] = CUDART_INF_F;
        bestI[i] = 0x7fffffff;
    }

    float acc[8][8];

    for (int nt = 0; nt < NS_TILES; nt++) {
        const int nBase = NT_CODES + nt * 128;
        #pragma unroll
        for (int i = 0; i < 8; i++)
            #pragma unroll
            for (int j = 0; j < 8; j++) acc[i][j] = 0.f;

        for (int k0 = 0; k0 < DIM; k0 += 16) {
            BAR_S();
            // A tile: 64 rows x 16 k, transposed
            size_t abase = ((size_t)(mBase + lrowA) * DIM + k0) >> 2;
            float4 av0 = Xv[abase + lkpA];
            float4 av1 = Xv[abase + lkpA + 1];
            sAs[(lkpA * 4 + 0) * 64 + lrowA] = av0.x;
            sAs[(lkpA * 4 + 1) * 64 + lrowA] = av0.y;
            sAs[(lkpA * 4 + 2) * 64 + lrowA] = av0.z;
            sAs[(lkpA * 4 + 3) * 64 + lrowA] = av0.w;
            sAs[(lkpA * 4 + 4) * 64 + lrowA] = av1.x;
            sAs[(lkpA * 4 + 5) * 64 + lrowA] = av1.y;
            sAs[(lkpA * 4 + 6) * 64 + lrowA] = av1.z;
            sAs[(lkpA * 4 + 7) * 64 + lrowA] = av1.w;
            // B tile: 128 codes x 16 k, transposed (each thread one code row)
            size_t bbase = ((size_t)(nBase + ctid) * DIM + k0) >> 2;
            #pragma unroll
            for (int q = 0; q < 4; q++) {
                float4 bv = Ev[bbase + q];
                sBs[(q * 4 + 0) * 128 + ctid] = bv.x;
                sBs[(q * 4 + 1) * 128 + ctid] = bv.y;
                sBs[(q * 4 + 2) * 128 + ctid] = bv.z;
                sBs[(q * 4 + 3) * 128 + ctid] = bv.w;
            }
            BAR_S();

            #pragma unroll
            for (int kk = 0; kk < 16; kk++) {
                float4 a0 = *reinterpret_cast<const float4*>(&sAs[kk * 64 + ty * 8]);
                float4 a1 = *reinterpret_cast<const float4*>(&sAs[kk * 64 + ty * 8 + 4]);
                float4 b0 = *reinterpret_cast<const float4*>(&sBs[kk * 128 + tx * 8]);
                float4 b1 = *reinterpret_cast<const float4*>(&sBs[kk * 128 + tx * 8 + 4]);
                float a[8] = {a0.x, a0.y, a0.z, a0.w, a1.x, a1.y, a1.z, a1.w};
                float b[8] = {b0.x, b0.y, b0.z, b0.w, b1.x, b1.y, b1.z, b1.w};
                #pragma unroll
                for (int i = 0; i < 8; i++)
                    #pragma unroll
                    for (int j = 0; j < 8; j++)
                        acc[i][j] = __fmaf_rn(a[i], b[j], acc[i][j]);
            }
        }

        // epilogue: exact distances, register argmin, tighten shared rmin
        float sc[8];
        #pragma unroll
        for (int j = 0; j < 8; j++) sc[j] = g_codenorm[nBase + tx * 8 + j];
        #pragma unroll
        for (int i = 0; i < 8; i++) {
            const int rloc = ty * 8 + i;
            float lmin = CUDART_INF_F;
            #pragma unroll
            for (int j = 0; j < 8; j++) {
                float tt = __fadd_rn(cr[i], sc[j]);
                float d  = __fmaf_rn(-2.0f, acc[i][j], tt);
                int  idx = nBase + tx * 8 + j;
                if (d < bestD[i] || (d == bestD[i] && idx < bestI[i])) {
                    bestD[i] = d; bestI[i] = idx;
                }
                lmin = fminf(lmin, d);
            }
            atomicMin(reinterpret_cast<int*>(&rmin[rloc]), __float_as_int(lmin));
        }
    }

    // one packed-key global atomic per (row, tx): exact min + lowest-index tie
    #pragma unroll
    for (int i = 0; i < 8; i++) {
        unsigned long long key =
            ((unsigned long long)__float_as_uint(bestD[i]) << 32)
            | (unsigned int)bestI[i];
        atomicMin(&g_best[mBase + ty * 8 + i], key);
    }
}

// ---------------------------------------------------------------------------
// Kernel B: fused warp-specialized GEMM (tensor pipe + fma pipe concurrently)
// ---------------------------------------------------------------------------
__global__ __launch_bounds__(256, 2) void vq_fused_kernel(
        const float* __restrict__ X, const float* __restrict__ E) {
    extern __shared__ char smem[];
    const int tid  = threadIdx.x;
    const int cls  = tid >> 7;            // 0 = tensor warps, 1 = simt warps
    const int ctid = tid & 127;
    const int mBase = blockIdx.x * 64;
    const uint32_t sbase = smem_to_u32(smem);

    if (tid < 64)
        *reinterpret_cast<float*>(smem + OFF_RMIN + 4 * tid) = CUDART_INF_F;

    if (cls == 0) {
        const uint4* Xb4 = reinterpret_cast<const uint4*>(g_Xb);
        const uint4* Eb4 = reinterpret_cast<const uint4*>(g_Eb);
        #pragma unroll
        for (int n = 0; n < 32; n++) {
            int i = ctid + n * 128;
            int row = i >> 6, c = i & 63;
            uint32_t dst = sbase + OFF_A + row * 1024 + ((c ^ (row & 7)) << 4);
            CP_ASYNC16(dst, Xb4 + (size_t)(mBase + row) * 64 + c);
        }
        #pragma unroll
        for (int n = 0; n < 8; n++) {
            int i = ctid + n * 128;
            int r = i >> 3, c = i & 7;
            uint32_t dst = sbase + OFF_B + r * 128 + ((c ^ (r & 7)) << 4);
            CP_ASYNC16(dst, Eb4 + (size_t)r * 64 + c);
        }
        if (ctid < 32) {
            uint32_t dst = sbase + OFF_CN + ctid * 16;
            CP_ASYNC16(dst, reinterpret_cast<const uint4*>(g_codenorm) + ctid);
        }
        CP_COMMIT();
        #pragma unroll
        for (int n = 0; n < 8; n++) {
            int i = ctid + n * 128;
            int r = i >> 3, c = i & 7;
            uint32_t dst = sbase + OFF_B + 16384 + r * 128 + ((c ^ (r & 7)) << 4);
            CP_ASYNC16(dst, Eb4 + (size_t)r * 64 + 8 + c);
        }
        CP_COMMIT();
    }
    __syncthreads();                      // rmin + prologue visible to all

    if (cls == 0) tensor_body(smem, ctid, mBase);
    else          simt_body(smem, ctid, mBase, X, E);
}

// ---------------------------------------------------------------------------
// Kernel C: exact fp32 rerank over tensor candidates, merged with SIMT best
// ---------------------------------------------------------------------------
__global__ void rerank_kernel(const float* __restrict__ X, const float* __restrict__ E) {
    const int gw   = (blockIdx.x * blockDim.x + threadIdx.x) >> 5;
    const int lane = threadIdx.x & 31;
    if (gw >= NROWS) return;
    float xv[16];
    #pragma unroll
    for (int j = 0; j < 16; j++) xv[j] = X[(size_t)gw * DIM + j * 32 + lane];
    const float cr = g_rownorm[gw];
    const int cnt  = g_candCount[gw];
    float bd = CUDART_INF_F;
    int   bi = 0x7fffffff;
    if (cnt <= MAXC) {
        for (int c = 0; c < cnt; c++) {
            int idx = g_candIdx[(size_t)gw * MAXC + c];
            float s = 0.f;
            #pragma unroll
            for (int j = 0; j < 16; j++)
                s = __fmaf_rn(xv[j], E[(size_t)idx * DIM + j * 32 + lane], s);
            #pragma unroll
            for (int o = 16; o > 0; o >>= 1) s += __shfl_xor_sync(0xffffffffu, s, o);
            float t = __fadd_rn(cr, g_codenorm[idx]);
            float d = __fmaf_rn(-2.0f, s, t);
            if (d < bd || (d == bd && idx < bi)) { bd = d; bi = idx; }
        }
    } else {  // overflow fallback: exact scan of the TENSOR range only
        for (int idx = 0; idx < NT_CODES; idx++) {
            float s = 0.f;
            #pragma unroll
            for (int j = 0; j < 16; j++)
                s = __fmaf_rn(xv[j], E[(size_t)idx * DIM + j * 32 + lane], s);
            #pragma unroll
            for (int o = 16; o > 0; o >>= 1) s += __shfl_xor_sync(0xffffffffu, s, o);
            float t = __fadd_rn(cr, g_codenorm[idx]);
            float d = __fmaf_rn(-2.0f, s, t);
            if (d < bd || (d == bd && idx < bi)) { bd = d; bi = idx; }
        }
    }
    if (lane == 0) {
        // merge with SIMT-class exact best (codes NT_CODES..8191)
        unsigned long long pk = g_best[gw];
        float sd  = __uint_as_float((unsigned int)(pk >> 32));
        int  sidx = (int)(pk & 0xffffffffu);
        if (sd < bd || (sd == bd && sidx < bi)) { bd = sd; bi = sidx; }
        g_argmin[gw] = bi;
    }
}

// ---------------------------------------------------------------------------
// Kernel D: gather + quantized_out + indices + per-block loss partials
// ---------------------------------------------------------------------------
__global__ void output_kernel(const float* __restrict__ X, const float* __restrict__ E,
                              float* __restrict__ out) {
    const int tid    = blockIdx.x * blockDim.x + threadIdx.x;
    const int stride = gridDim.x * blockDim.x;
    const float4* __restrict__ Xv = reinterpret_cast<const float4*>(X);
    const float4* __restrict__ Ev = reinterpret_cast<const float4*>(E);
    float4* __restrict__ Ov = reinterpret_cast<float4*>(out);

    double lsum = 0.0;
    for (int e4 = tid; e4 < NELEM / 4; e4 += stride) {
        int row = e4 >> 7;
        int d4  = e4 & 127;
        int idx = g_argmin[row];
        float4 q = Ev[(size_t)idx * 128 + d4];
        float4 x = Xv[e4];
        float4 o; float r;
        r = __fsub_rn(q.x, x.x); o.x = __fadd_rn(__fmul_rn(x.x, 0.95f), __fmul_rn(r, 0.05f)); lsum += (double)__fmul_rn(r, r);
        r = __fsub_rn(q.y, x.y); o.y = __fadd_rn(__fmul_rn(x.y, 0.95f), __fmul_rn(r, 0.05f)); lsum += (double)__fmul_rn(r, r);
        r = __fsub_rn(q.z, x.z); o.z = __fadd_rn(__fmul_rn(x.z, 0.95f), __fmul_rn(r, 0.05f)); lsum += (double)__fmul_rn(r, r);
        r = __fsub_rn(q.w, x.w); o.w = __fadd_rn(__fmul_rn(x.w, 0.95f), __fmul_rn(r, 0.05f)); lsum += (double)__fmul_rn(r, r);
        Ov[e4] = o;
    }
    for (int r0 = tid; r0 < NROWS; r0 += stride)
        out[NELEM + r0] = (float)g_argmin[r0];

    __shared__ double sd[256];
    sd[threadIdx.x] = lsum;
    __syncthreads();
    #pragma unroll
    for (int o = 128; o > 0; o >>= 1) {
        if (threadIdx.x < o) sd[threadIdx.x] += sd[threadIdx.x + o];
        __syncthreads();
    }
    if (threadIdx.x == 0) g_partial[blockIdx.x] = sd[0];
}

// ---------------------------------------------------------------------------
// Kernel E: deterministic final loss reduction
// ---------------------------------------------------------------------------
__global__ void loss_kernel(float* __restrict__ out) {
    __shared__ double sd[256];
    double v = 0.0;
    for (int i = threadIdx.x; i < LOSS_PARTIALS; i += 256) v += g_partial[i];
    sd[threadIdx.x] = v;
    __syncthreads();
    #pragma unroll
    for (int o = 128; o > 0; o >>= 1) {
        if (threadIdx.x < o) sd[threadIdx.x] += sd[threadIdx.x + o];
        __syncthreads();
    }
    if (threadIdx.x == 0)
        out[NELEM + NROWS] = (float)(1.25 * (sd[0] / (double)NELEM));
}

// ---------------------------------------------------------------------------
extern "C" void kernel_launch(void* const* d_in, const int* in_sizes, int n_in,
                              void* d_out, int out_size) {
    const float* X = (const float*)d_in[0];   // [32768, 512]
    const float* E = (const float*)d_in[1];   // [8192, 512]
    float* out = (float*)d_out;

    cudaFuncSetAttribute(vq_fused_kernel,
                         cudaFuncAttributeMaxDynamicSharedMemorySize, FUSED_SMEM);

    convert_kernel<<<(NELEM / 4 + NCODES * DIM / 4) / 256, 256>>>(X, E);
    norms_kernel<<<(NROWS + NCODES) / 8, 256>>>(X, E);
    vq_fused_kernel<<<NROWS / 64, 256, FUSED_SMEM>>>(X, E);
    rerank_kernel<<<NROWS / 8, 256>>>(X, E);
    output_kernel<<<2048, 256>>>(X, E, out);
    loss_kernel<<<1, 256>>>(out);
}

// round 17
// speedup vs baseline: 1.1853x; 1.1853x over previous
#include <cuda_runtime.h>
#include <cuda_bf16.h>
#include <math_constants.h>
#include <cstdint>

#define NROWS 32768
#define NCODES 8192
#define DIM 512
#define NELEM (NROWS * DIM)          // 16777216
#define LOSS_PARTIALS 2048
#define MAXC 128
#define MARGIN 4e-4f

#define NT_TILES 48                  // tensor-class n-tiles (codes 0..6143)
#define NT_CODES (NT_TILES * 128)
#define NS_TILES 16                  // SIMT-class n-tiles (codes 6144..8191)

// ---------------------------------------------------------------------------
// Device globals (scratch; no runtime allocation allowed)
// ---------------------------------------------------------------------------
__device__ __nv_bfloat16 g_Xb[(size_t)NROWS * DIM];   // ~33.5 MB
__device__ __nv_bfloat16 g_Eb[(size_t)NCODES * DIM];  // ~8.4 MB
__device__ float  g_rownorm[NROWS];
__device__ float  g_codenorm[NCODES];
__device__ int    g_argmin[NROWS];
__device__ int    g_candCount[NROWS];
__device__ int    g_candIdx[(size_t)NROWS * MAXC];    // 16.8 MB
__device__ unsigned long long g_best[NROWS];          // packed (dist_bits, idx)
__device__ double g_partial[LOSS_PARTIALS];

// ---------------------------------------------------------------------------
// Arch-neutral PTX helpers
// ---------------------------------------------------------------------------
__device__ __forceinline__ uint32_t smem_to_u32(const void* p) {
    uint32_t a;
    asm("{ .reg .u64 t; cvta.to.shared.u64 t, %1; cvt.u32.u64 %0, t; }"
        : "=r"(a) : "l"(p));
    return a;
}
#define CP_ASYNC16(dst, src) \
    asm volatile("cp.async.cg.shared.global [%0], [%1], 16;" :: "r"(dst), "l"(src) : "memory")
#define CP_COMMIT() asm volatile("cp.async.commit_group;" ::: "memory")
#define CP_WAIT1()  asm volatile("cp.async.wait_group 1;" ::: "memory")
#define BAR_T() asm volatile("bar.sync 1, 128;" ::: "memory")   // tensor warps 0-3
#define BAR_S() asm volatile("bar.sync 2, 128;" ::: "memory")   // simt warps 4-7

__device__ __forceinline__ void ldsm_x4(uint32_t* r, uint32_t addr) {
    asm volatile("ldmatrix.sync.aligned.m8n8.x4.shared.b16 {%0,%1,%2,%3}, [%4];"
        : "=r"(r[0]), "=r"(r[1]), "=r"(r[2]), "=r"(r[3]) : "r"(addr));
}
__device__ __forceinline__ void mma16816(float* c, const uint32_t* a, const uint32_t* b) {
    asm volatile(
        "mma.sync.aligned.m16n8k16.row.col.f32.bf16.bf16.f32 "
        "{%0,%1,%2,%3}, {%4,%5,%6,%7}, {%8,%9}, {%0,%1,%2,%3};"
        : "+f"(c[0]), "+f"(c[1]), "+f"(c[2]), "+f"(c[3])
        : "r"(a[0]), "r"(a[1]), "r"(a[2]), "r"(a[3]), "r"(b[0]), "r"(b[1]));
}

// smem layout (dynamic). 111,872 B -> 2 CTAs/SM.
#define OFF_A     0         // tensor A: 64 x 512 bf16, XOR-swizzled = 65536 B
#define OFF_B     65536     // tensor B: 2 x (128 x 64 bf16)         = 32768 B
#define OFF_CN    98304     // 2 x 128 floats codenorm               =  1024 B
#define OFF_RMIN  99328     // 64 floats running row-min (shared)    =   256 B
#define OFF_SAS   99584     // simt As: 16 x 64 fp32                 =  4096 B
#define OFF_SBS   103680    // simt Bs: 16 x 128 fp32                =  8192 B
#define FUSED_SMEM 111872

// ---------------------------------------------------------------------------
// Kernel 0: fp32 -> bf16 conversion (+ init candidate counters / g_best)
// ---------------------------------------------------------------------------
__global__ void convert_kernel(const float* __restrict__ X, const float* __restrict__ E) {
    const int t  = blockIdx.x * blockDim.x + threadIdx.x;
    const int nX = NELEM / 4;
    const int nE = NCODES * DIM / 4;
    if (t < nX) {
        float4 v = reinterpret_cast<const float4*>(X)[t];
        __nv_bfloat162 p0, p1;
        p0.x = __float2bfloat16_rn(v.x); p0.y = __float2bfloat16_rn(v.y);
        p1.x = __float2bfloat16_rn(v.z); p1.y = __float2bfloat16_rn(v.w);
        reinterpret_cast<__nv_bfloat162*>(g_Xb)[t * 2]     = p0;
        reinterpret_cast<__nv_bfloat162*>(g_Xb)[t * 2 + 1] = p1;
    } else if (t < nX + nE) {
        int u = t - nX;
        float4 v = reinterpret_cast<const float4*>(E)[u];
        __nv_bfloat162 p0, p1;
        p0.x = __float2bfloat16_rn(v.x); p0.y = __float2bfloat16_rn(v.y);
        p1.x = __float2bfloat16_rn(v.z); p1.y = __float2bfloat16_rn(v.w);
        reinterpret_cast<__nv_bfloat162*>(g_Eb)[u * 2]     = p0;
        reinterpret_cast<__nv_bfloat162*>(g_Eb)[u * 2 + 1] = p1;
    }
    if (t < NROWS) {
        g_candCount[t] = 0;
        g_best[t] = 0xFFFFFFFFFFFFFFFFull;
    }
}

// ---------------------------------------------------------------------------
// Kernel A: row norms of X and code norms of E (one warp per vector)
// ---------------------------------------------------------------------------
__global__ void norms_kernel(const float* __restrict__ X, const float* __restrict__ E) {
    int gwarp = (blockIdx.x * blockDim.x + threadIdx.x) >> 5;
    int lane  = threadIdx.x & 31;
    const float* p;
    if (gwarp < NROWS)                p = X + (size_t)gwarp * DIM;
    else if (gwarp < NROWS + NCODES)  p = E + (size_t)(gwarp - NROWS) * DIM;
    else return;
    float s = 0.f;
    #pragma unroll
    for (int t = 0; t < DIM / 32; t++) { float v = p[lane + t * 32]; s = __fmaf_rn(v, v, s); }
    #pragma unroll
    for (int o = 16; o > 0; o >>= 1) s += __shfl_xor_sync(0xffffffffu, s, o);
    if (lane == 0) {
        if (gwarp < NROWS) g_rownorm[gwarp] = s;
        else               g_codenorm[gwarp - NROWS] = s;
    }
}

// ---------------------------------------------------------------------------
// Tensor-class body (warps 0-3): 4-warp machinery (warp tile 32x64),
//   codes [0, NT_CODES), margin-candidate output.
// ---------------------------------------------------------------------------
__device__ void tensor_body(char* smem, int ctid, int mBase) {
    const int wid  = ctid >> 5;           // 0..3
    const int lane = ctid & 31;
    const int wm   = wid & 1;             // warp row block (32 rows)
    const int wn   = wid >> 1;            // warp col block (64 cols), 0..1
    const uint32_t sbase = smem_to_u32(smem);
    float* rmin = reinterpret_cast<float*>(smem + OFF_RMIN);
    const uint4* Eb4 = reinterpret_cast<const uint4*>(g_Eb);

    float cr[4];
    #pragma unroll
    for (int mi = 0; mi < 2; mi++)
        #pragma unroll
        for (int h = 0; h < 2; h++)
            cr[mi * 2 + h] = g_rownorm[mBase + wm * 32 + mi * 16 + (lane >> 2) + h * 8];

    uint32_t aBase[2]; int aS[2];
    #pragma unroll
    for (int mi = 0; mi < 2; mi++) {
        int row = wm * 32 + mi * 16 + (lane & 7) + ((lane >> 3) & 1) * 8;
        aBase[mi] = sbase + OFF_A + row * 1024;
        aS[mi] = row & 7;
    }
    uint32_t bRow[4]; int bS[4];
    #pragma unroll
    for (int np = 0; np < 4; np++) {
        int n = wn * 64 + np * 16 + (lane & 7) + ((lane >> 4) & 1) * 8;
        bRow[np] = n * 128;
        bS[np] = n & 7;
    }
    const int aCb = (lane >> 4) & 1;
    const int bCb = (lane >> 3) & 1;

    float acc[2][8][4];
    const int NCHUNK = NT_TILES * 8;          // 384

    for (int t = 0; t < NCHUNK; t++) {
        CP_WAIT1();
        BAR_T();

        const int kc = t & 7;
        if (kc == 0) {
            #pragma unroll
            for (int mi = 0; mi < 2; mi++)
                #pragma unroll
                for (int j = 0; j < 8; j++)
                    #pragma unroll
                    for (int q = 0; q < 4; q++) acc[mi][j][q] = 0.f;
        }

        const uint32_t bBufBase = sbase + OFF_B + (t & 1) * 16384;
        #pragma unroll
        for (int ks = 0; ks < 4; ks++) {
            uint32_t a[2][4], b[4][4];
            const int aC = kc * 8 + ks * 2 + aCb;
            const int bC = ks * 2 + bCb;
            #pragma unroll
            for (int mi = 0; mi < 2; mi++)
                ldsm_x4(a[mi], aBase[mi] + ((aC ^ aS[mi]) << 4));
            #pragma unroll
            for (int np = 0; np < 4; np++)
                ldsm_x4(b[np], bBufBase + bRow[np] + ((bC ^ bS[np]) << 4));
            #pragma unroll
            for (int mi = 0; mi < 2; mi++)
                #pragma unroll
                for (int np = 0; np < 4; np++) {
                    mma16816(acc[mi][np * 2],     a[mi], &b[np][0]);
                    mma16816(acc[mi][np * 2 + 1], a[mi], &b[np][2]);
                }
        }

        if (kc == 7) {
            const int nt = t >> 3;
            const float* cn = reinterpret_cast<const float*>(smem + OFF_CN + (nt & 1) * 512);
            #pragma unroll
            for (int mi = 0; mi < 2; mi++) {
                #pragma unroll
                for (int h = 0; h < 2; h++) {
                    const int rloc = wm * 32 + mi * 16 + (lane >> 2) + h * 8;
                    const float crv = cr[mi * 2 + h];
                    const float rm  = rmin[rloc];
                    float d[16];
                    float lmin = CUDART_INF_F;
                    #pragma unroll
                    for (int j = 0; j < 8; j++) {
                        #pragma unroll
                        for (int cb = 0; cb < 2; cb++) {
                            float sc = cn[wn * 64 + j * 8 + (lane & 3) * 2 + cb];
                            float v = __fmaf_rn(-2.0f, acc[mi][j][h * 2 + cb], crv + sc);
                            d[j * 2 + cb] = v;
                            lmin = fminf(lmin, v);
                        }
                    }
                    const float thr = fminf(rm, lmin) + MARGIN;
                    bool has = false;
                    #pragma unroll
                    for (int j = 0; j < 16; j++) has |= (d[j] < thr);
                    if (__any_sync(0xffffffffu, has)) {
                        #pragma unroll
                        for (int j = 0; j < 16; j++) {
                            if (d[j] < thr) {
                                int idx  = nt * 128 + wn * 64 + (j >> 1) * 8 + (lane & 3) * 2 + (j & 1);
                                int grow = mBase + rloc;
                                int pos = atomicAdd(&g_candCount[grow], 1);
                                if (pos < MAXC) g_candIdx[(size_t)grow * MAXC + pos] = idx;
                            }
                        }
                    }
                    float m2 = fminf(lmin, __shfl_xor_sync(0xffffffffu, lmin, 1));
                    m2 = fminf(m2, __shfl_xor_sync(0xffffffffu, m2, 2));
                    if ((lane & 3) == 0)
                        atomicMin(reinterpret_cast<int*>(&rmin[rloc]), __float_as_int(m2));
                }
            }
        }

        BAR_T();                              // tensor warps done reading buffer t&1

        if (t + 2 < NCHUNK) {
            const int tn = t + 2, ntn = tn >> 3, kcn = tn & 7;
            #pragma unroll
            for (int n = 0; n < 8; n++) {
                int i = ctid + n * 128;
                int r = i >> 3, c = i & 7;
                uint32_t dst = sbase + OFF_B + (t & 1) * 16384 + r * 128 + ((c ^ (r & 7)) << 4);
                CP_ASYNC16(dst, Eb4 + (size_t)(ntn * 128 + r) * 64 + kcn * 8 + c);
            }
            if (kcn == 0 && ctid < 32) {
                uint32_t dst = sbase + OFF_CN + (ntn & 1) * 512 + ctid * 16;
                CP_ASYNC16(dst, reinterpret_cast<const uint4*>(g_codenorm + ntn * 128) + ctid);
            }
        }
        CP_COMMIT();
    }
}

// ---------------------------------------------------------------------------
// SIMT-class body (warps 4-7): exact fp32 FFMA, codes [NT_CODES, 8192).
//   Register-resident argmin (reference tie-break); ONE packed atomicMin per
//   (row, column-group) at the end.
// ---------------------------------------------------------------------------
__device__ void simt_body(char* smem, int ctid, int mBase,
                          const float* __restrict__ X, const float* __restrict__ E) {
    float* sAs = reinterpret_cast<float*>(smem + OFF_SAS);   // [16][64]
    float* sBs = reinterpret_cast<float*>(smem + OFF_SBS);   // [16][128]
    float* rmin = reinterpret_cast<float*>(smem + OFF_RMIN);

    const int tx = ctid & 15;          // 16 col groups (8 codes each)
    const int ty = ctid >> 4;          // 8 row groups (8 rows each)

    const int lrowA = ctid >> 1;       // 0..63
    const int lkpA  = (ctid & 1) * 2;  // 0 or 2

    const float4* __restrict__ Xv = reinterpret_cast<const float4*>(X);
    const float4* __restrict__ Ev = reinterpret_cast<const float4*>(E);

    float cr[8];
    float bestD[8];
    int   bestI[8];
    #pragma unroll
    for (int i = 0; i < 8; i++) {
        cr[i]    = g_rownorm[mBase + ty * 8 + i];
        bestD[i] = CUDART_INF_F;
        bestI[i] = 0x7fffffff;
    }

    float acc[8][8];

    for (int nt = 0; nt < NS_TILES; nt++) {
        const int nBase = NT_CODES + nt * 128;
        #pragma unroll
        for (int i = 0; i < 8; i++)
            #pragma unroll
            for (int j = 0; j < 8; j++) acc[i][j] = 0.f;

        for (int k0 = 0; k0 < DIM; k0 += 16) {
            BAR_S();
            // A tile: 64 rows x 16 k, transposed
            size_t abase = ((size_t)(mBase + lrowA) * DIM + k0) >> 2;
            float4 av0 = Xv[abase + lkpA];
            float4 av1 = Xv[abase + lkpA + 1];
            sAs[(lkpA * 4 + 0) * 64 + lrowA] = av0.x;
            sAs[(lkpA * 4 + 1) * 64 + lrowA] = av0.y;
            sAs[(lkpA * 4 + 2) * 64 + lrowA] = av0.z;
            sAs[(lkpA * 4 + 3) * 64 + lrowA] = av0.w;
            sAs[(lkpA * 4 + 4) * 64 + lrowA] = av1.x;
            sAs[(lkpA * 4 + 5) * 64 + lrowA] = av1.y;
            sAs[(lkpA * 4 + 6) * 64 + lrowA] = av1.z;
            sAs[(lkpA * 4 + 7) * 64 + lrowA] = av1.w;
            // B tile: 128 codes x 16 k, transposed (each thread one code row)
            size_t bbase = ((size_t)(nBase + ctid) * DIM + k0) >> 2;
            #pragma unroll
            for (int q = 0; q < 4; q++) {
                float4 bv = Ev[bbase + q];
                sBs[(q * 4 + 0) * 128 + ctid] = bv.x;
                sBs[(q * 4 + 1) * 128 + ctid] = bv.y;
                sBs[(q * 4 + 2) * 128 + ctid] = bv.z;
                sBs[(q * 4 + 3) * 128 + ctid] = bv.w;
            }
            BAR_S();

            #pragma unroll
            for (int kk = 0; kk < 16; kk++) {
                float4 a0 = *reinterpret_cast<const float4*>(&sAs[kk * 64 + ty * 8]);
                float4 a1 = *reinterpret_cast<const float4*>(&sAs[kk * 64 + ty * 8 + 4]);
                float4 b0 = *reinterpret_cast<const float4*>(&sBs[kk * 128 + tx * 8]);
                float4 b1 = *reinterpret_cast<const float4*>(&sBs[kk * 128 + tx * 8 + 4]);
                float a[8] = {a0.x, a0.y, a0.z, a0.w, a1.x, a1.y, a1.z, a1.w};
                float b[8] = {b0.x, b0.y, b0.z, b0.w, b1.x, b1.y, b1.z, b1.w};
                #pragma unroll
                for (int i = 0; i < 8; i++)
                    #pragma unroll
                    for (int j = 0; j < 8; j++)
                        acc[i][j] = __fmaf_rn(a[i], b[j], acc[i][j]);
            }
        }

        // epilogue: exact distances, register argmin, tighten shared rmin
        float sc[8];
        #pragma unroll
        for (int j = 0; j < 8; j++) sc[j] = g_codenorm[nBase + tx * 8 + j];
        #pragma unroll
        for (int i = 0; i < 8; i++) {
            const int rloc = ty * 8 + i;
            float lmin = CUDART_INF_F;
            #pragma unroll
            for (int j = 0; j < 8; j++) {
                float tt = __fadd_rn(cr[i], sc[j]);
                float d  = __fmaf_rn(-2.0f, acc[i][j], tt);
                int  idx = nBase + tx * 8 + j;
                if (d < bestD[i] || (d == bestD[i] && idx < bestI[i])) {
                    bestD[i] = d; bestI[i] = idx;
                }
                lmin = fminf(lmin, d);
            }
            atomicMin(reinterpret_cast<int*>(&rmin[rloc]), __float_as_int(lmin));
        }
    }

    // one packed-key global atomic per (row, tx): exact min + lowest-index tie
    #pragma unroll
    for (int i = 0; i < 8; i++) {
        unsigned long long key =
            ((unsigned long long)__float_as_uint(bestD[i]) << 32)
            | (unsigned int)bestI[i];
        atomicMin(&g_best[mBase + ty * 8 + i], key);
    }
}

// ---------------------------------------------------------------------------
// Kernel B: fused warp-specialized GEMM (tensor pipe + fma pipe concurrently)
// ---------------------------------------------------------------------------
__global__ __launch_bounds__(256, 2) void vq_fused_kernel(
        const float* __restrict__ X, const float* __restrict__ E) {
    extern __shared__ char smem[];
    const int tid  = threadIdx.x;
    const int cls  = tid >> 7;            // 0 = tensor warps, 1 = simt warps
    const int ctid = tid & 127;
    const int mBase = blockIdx.x * 64;
    const uint32_t sbase = smem_to_u32(smem);

    if (tid < 64)
        *reinterpret_cast<float*>(smem + OFF_RMIN + 4 * tid) = CUDART_INF_F;

    if (cls == 0) {
        const uint4* Xb4 = reinterpret_cast<const uint4*>(g_Xb);
        const uint4* Eb4 = reinterpret_cast<const uint4*>(g_Eb);
        #pragma unroll
        for (int n = 0; n < 32; n++) {
            int i = ctid + n * 128;
            int row = i >> 6, c = i & 63;
            uint32_t dst = sbase + OFF_A + row * 1024 + ((c ^ (row & 7)) << 4);
            CP_ASYNC16(dst, Xb4 + (size_t)(mBase + row) * 64 + c);
        }
        #pragma unroll
        for (int n = 0; n < 8; n++) {
            int i = ctid + n * 128;
            int r = i >> 3, c = i & 7;
            uint32_t dst = sbase + OFF_B + r * 128 + ((c ^ (r & 7)) << 4);
            CP_ASYNC16(dst, Eb4 + (size_t)r * 64 + c);
        }
        if (ctid < 32) {
            uint32_t dst = sbase + OFF_CN + ctid * 16;
            CP_ASYNC16(dst, reinterpret_cast<const uint4*>(g_codenorm) + ctid);
        }
        CP_COMMIT();
        #pragma unroll
        for (int n = 0; n < 8; n++) {
            int i = ctid + n * 128;
            int r = i >> 3, c = i & 7;
            uint32_t dst = sbase + OFF_B + 16384 + r * 128 + ((c ^ (r & 7)) << 4);
            CP_ASYNC16(dst, Eb4 + (size_t)r * 64 + 8 + c);
        }
        CP_COMMIT();
    }
    __syncthreads();                      // rmin + prologue visible to all

    if (cls == 0) tensor_body(smem, ctid, mBase);
    else          simt_body(smem, ctid, mBase, X, E);
}

// ---------------------------------------------------------------------------
// Kernel C: exact fp32 rerank over tensor candidates, merged with SIMT best
// ---------------------------------------------------------------------------
__global__ void rerank_kernel(const float* __restrict__ X, const float* __restrict__ E) {
    const int gw   = (blockIdx.x * blockDim.x + threadIdx.x) >> 5;
    const int lane = threadIdx.x & 31;
    if (gw >= NROWS) return;
    float xv[16];
    #pragma unroll
    for (int j = 0; j < 16; j++) xv[j] = X[(size_t)gw * DIM + j * 32 + lane];
    const float cr = g_rownorm[gw];
    const int cnt  = g_candCount[gw];
    float bd = CUDART_INF_F;
    int   bi = 0x7fffffff;
    if (cnt <= MAXC) {
        for (int c = 0; c < cnt; c++) {
            int idx = g_candIdx[(size_t)gw * MAXC + c];
            float s = 0.f;
            #pragma unroll
            for (int j = 0; j < 16; j++)
                s = __fmaf_rn(xv[j], E[(size_t)idx * DIM + j * 32 + lane], s);
            #pragma unroll
            for (int o = 16; o > 0; o >>= 1) s += __shfl_xor_sync(0xffffffffu, s, o);
            float t = __fadd_rn(cr, g_codenorm[idx]);
            float d = __fmaf_rn(-2.0f, s, t);
            if (d < bd || (d == bd && idx < bi)) { bd = d; bi = idx; }
        }
    } else {  // overflow fallback: exact scan of the TENSOR range only
        for (int idx = 0; idx < NT_CODES; idx++) {
            float s = 0.f;
            #pragma unroll
            for (int j = 0; j < 16; j++)
                s = __fmaf_rn(xv[j], E[(size_t)idx * DIM + j * 32 + lane], s);
            #pragma unroll
            for (int o = 16; o > 0; o >>= 1) s += __shfl_xor_sync(0xffffffffu, s, o);
            float t = __fadd_rn(cr, g_codenorm[idx]);
            float d = __fmaf_rn(-2.0f, s, t);
            if (d < bd || (d == bd && idx < bi)) { bd = d; bi = idx; }
        }
    }
    if (lane == 0) {
        // merge with SIMT-class exact best (codes NT_CODES..8191)
        unsigned long long pk = g_best[gw];
        float sd  = __uint_as_float((unsigned int)(pk >> 32));
        int  sidx = (int)(pk & 0xffffffffu);
        if (sd < bd || (sd == bd && sidx < bi)) { bd = sd; bi = sidx; }
        g_argmin[gw] = bi;
    }
}

// ---------------------------------------------------------------------------
// Kernel D: gather + quantized_out + indices + per-block loss partials
// ---------------------------------------------------------------------------
__global__ void output_kernel(const float* __restrict__ X, const float* __restrict__ E,
                              float* __restrict__ out) {
    const int tid    = blockIdx.x * blockDim.x + threadIdx.x;
    const int stride = gridDim.x * blockDim.x;
    const float4* __restrict__ Xv = reinterpret_cast<const float4*>(X);
    const float4* __restrict__ Ev = reinterpret_cast<const float4*>(E);
    float4* __restrict__ Ov = reinterpret_cast<float4*>(out);

    double lsum = 0.0;
    for (int e4 = tid; e4 < NELEM / 4; e4 += stride) {
        int row = e4 >> 7;
        int d4  = e4 & 127;
        int idx = g_argmin[row];
        float4 q = Ev[(size_t)idx * 128 + d4];
        float4 x = Xv[e4];
        float4 o; float r;
        r = __fsub_rn(q.x, x.x); o.x = __fadd_rn(__fmul_rn(x.x, 0.95f), __fmul_rn(r, 0.05f)); lsum += (double)__fmul_rn(r, r);
        r = __fsub_rn(q.y, x.y); o.y = __fadd_rn(__fmul_rn(x.y, 0.95f), __fmul_rn(r, 0.05f)); lsum += (double)__fmul_rn(r, r);
        r = __fsub_rn(q.z, x.z); o.z = __fadd_rn(__fmul_rn(x.z, 0.95f), __fmul_rn(r, 0.05f)); lsum += (double)__fmul_rn(r, r);
        r = __fsub_rn(q.w, x.w); o.w = __fadd_rn(__fmul_rn(x.w, 0.95f), __fmul_rn(r, 0.05f)); lsum += (double)__fmul_rn(r, r);
        Ov[e4] = o;
    }
    for (int r0 = tid; r0 < NROWS; r0 += stride)
        out[NELEM + r0] = (float)g_argmin[r0];

    __shared__ double sd[256];
    sd[threadIdx.x] = lsum;
    __syncthreads();
    #pragma unroll
    for (int o = 128; o > 0; o >>= 1) {
        if (threadIdx.x < o) sd[threadIdx.x] += sd[threadIdx.x + o];
        __syncthreads();
    }
    if (threadIdx.x == 0) g_partial[blockIdx.x] = sd[0];
}

// ---------------------------------------------------------------------------
// Kernel E: deterministic final loss reduction
// ---------------------------------------------------------------------------
__global__ void loss_kernel(float* __restrict__ out) {
    __shared__ double sd[256];
    double v = 0.0;
    for (int i = threadIdx.x; i < LOSS_PARTIALS; i += 256) v += g_partial[i];
    sd[threadIdx.x] = v;
    __syncthreads();
    #pragma unroll
    for (int o = 128; o > 0; o >>= 1) {
        if (threadIdx.x < o) sd[threadIdx.x] += sd[threadIdx.x + o];
        __syncthreads();
    }
    if (threadIdx.x == 0)
        out[NELEM + NROWS] = (float)(1.25 * (sd[0] / (double)NELEM));
}

// ---------------------------------------------------------------------------
extern "C" void kernel_launch(void* const* d_in, const int* in_sizes, int n_in,
                              void* d_out, int out_size) {
    const float* X = (const float*)d_in[0];   // [32768, 512]
    const float* E = (const float*)d_in[1];   // [8192, 512]
    float* out = (float*)d_out;

    cudaFuncSetAttribute(vq_fused_kernel,
                         cudaFuncAttributeMaxDynamicSharedMemorySize, FUSED_SMEM);

    convert_kernel<<<(NELEM / 4 + NCODES * DIM / 4) / 256, 256>>>(X, E);
    norms_kernel<<<(NROWS + NCODES) / 8, 256>>>(X, E);
    vq_fused_kernel<<<NROWS / 64, 256, FUSED_SMEM>>>(X, E);
    rerank_kernel<<<NROWS / 8, 256>>>(X, E);
    output_kernel<<<2048, 256>>>(X, E, out);
    loss_kernel<<<1, 256>>>(out);
}